// round 17
// baseline (speedup 1.0000x reference)
#include <cuda_runtime.h>
#include <cuda_fp16.h>
#include <stdint.h>

// out[r,o] = tanh(scale(r) * dot(enc_row(r), W[o,:]) + b[o])
//   r = b*128 + m (m = l*4+n, l<32) -> M=4096 ; enc phys row = b*2048 + m
//   K=256, N=256. (Spectral DCT/mask/IDCT collapses to mask*enc since the
//   band mask is independent of the DCT index.)
//
// Round 17: TWO kernels in the graph.
//  K1 (convert): used enc rows + W -> fp16 in __device__ scratch. Pure
//     streaming, ~1us, no sync structure.
//  K2 (GEMM): fp16 loads GMEM->SMEM via cp.async (no register staging, no
//     conversion, no commit phase -- the 2.5-3us serial prologue of R11-16
//     collapses to an async volley + wait_group). Mainloop = proven R13
//     shape: 16 warps 4(M:32)x4(N:16), fragment double-buffered, 16 k16
//     iters, zero mid-loop barriers. smem 96KB, grid (32,4) = 1 wave.
// fp16 HMMA m16n8k16 fp32-accum, A and B single fp16: rel err ~3.2e-4.

#define THREADS 512
#define OFF_A 0
#define OFF_B 65536
#define DYN_SMEM 98304

__device__ __half g_encH[4096 * 256];   // logical rows r = bx*128+m
__device__ __half g_wH[256 * 256];

static __device__ __forceinline__ uint32_t smem_u32(const void* p) {
    uint32_t a;
    asm("{ .reg .u64 t; cvta.to.shared.u64 t, %1; cvt.u32.u64 %0, t; }"
        : "=r"(a) : "l"(p));
    return a;
}

static __device__ __forceinline__ void ldmx4(uint32_t* r, uint32_t addr) {
    asm volatile("ldmatrix.sync.aligned.m8n8.x4.shared.b16 {%0,%1,%2,%3}, [%4];"
                 : "=r"(r[0]), "=r"(r[1]), "=r"(r[2]), "=r"(r[3]) : "r"(addr));
}

static __device__ __forceinline__ void mma16816(float* c, const uint32_t* a,
                                                uint32_t b0, uint32_t b1) {
    asm volatile(
        "mma.sync.aligned.m16n8k16.row.col.f32.f16.f16.f32 "
        "{%0,%1,%2,%3},{%4,%5,%6,%7},{%8,%9},{%0,%1,%2,%3};"
        : "+f"(c[0]), "+f"(c[1]), "+f"(c[2]), "+f"(c[3])
        : "r"(a[0]), "r"(a[1]), "r"(a[2]), "r"(a[3]), "r"(b0), "r"(b1));
}

static __device__ __forceinline__ void cp16(uint32_t smem_dst, const void* gsrc) {
    asm volatile("cp.async.cg.shared.global [%0], [%1], 16;"
                 :: "r"(smem_dst), "l"(gsrc) : "memory");
}

static __device__ __forceinline__ float tanh_fast(float x) {
    float e = __expf(2.0f * x);
    return 1.0f - __fdividef(2.0f, e + 1.0f);
}

static __device__ __forceinline__ uint4 cvt8_h(const float4& v0, const float4& v1) {
    __half2 h0 = __floats2half2_rn(v0.x, v0.y);
    __half2 h1 = __floats2half2_rn(v0.z, v0.w);
    __half2 h2 = __floats2half2_rn(v1.x, v1.y);
    __half2 h3 = __floats2half2_rn(v1.z, v1.w);
    return make_uint4(*(uint32_t*)&h0, *(uint32_t*)&h1,
                      *(uint32_t*)&h2, *(uint32_t*)&h3);
}

// ---- K1: convert used enc rows + W to fp16 scratch (8 elems/thread)
__global__ __launch_bounds__(256) void cvt_kernel(
    const float* __restrict__ enc, const float* __restrict__ W)
{
    const int g = blockIdx.x * 256 + threadIdx.x;
    if (g < 131072) {                     // enc: 4096 rows x 32 units
        const int r = g >> 5;             // logical row 0..4095
        const int u = g & 31;             // 8-elem unit
        const int phys = (r >> 7) * 2048 + (r & 127);
        const float4* src = (const float4*)enc + (size_t)phys * 64 + u * 2;
        float4 v0 = src[0], v1 = src[1];
        *(uint4*)(g_encH + (size_t)r * 256 + u * 8) = cvt8_h(v0, v1);
    } else {                              // W: 256 rows x 32 units
        const int g2 = g - 131072;        // 0..8191
        const int r = g2 >> 5;
        const int u = g2 & 31;
        const float4* src = (const float4*)W + (size_t)r * 64 + u * 2;
        float4 v0 = src[0], v1 = src[1];
        *(uint4*)(g_wH + (size_t)r * 256 + u * 8) = cvt8_h(v0, v1);
    }
}

// ---- K2: GEMM + epilogue
__global__ __launch_bounds__(THREADS, 1) void spectral_hmma_kernel(
    const float* __restrict__ bias,
    float* __restrict__ out)
{
    extern __shared__ __align__(16) uint8_t dyn[];
    const uint32_t sbase = smem_u32(dyn);

    const int tid = threadIdx.x;
    const int wid = tid >> 5;
    const int lid = tid & 31;
    const int bx = blockIdx.x;   // M tile (128 rows), 0..31
    const int by = blockIdx.y;   // N tile (64 cols), 0..3

    // ---- cp.async volley: A 4096 16B-units (8/thread), B 2048 (4/thread)
    #pragma unroll
    for (int s = 0; s < 8; ++s) {
        const int g = tid + s * 512;
        const int row = g >> 5;          // 0..127
        const int ck  = g & 31;
        uint32_t sw = sbase + OFF_A + row * 512
                    + (((ck ^ (row & 7)) & 31) << 4);
        cp16(sw, g_encH + ((size_t)(bx * 128 + row)) * 256 + ck * 8);
    }
    #pragma unroll
    for (int s = 0; s < 4; ++s) {
        const int g = tid + s * 512;
        const int row = g >> 5;          // 0..63
        const int ck  = g & 31;
        uint32_t sw = sbase + OFF_B + row * 512
                    + (((ck ^ (row & 7)) & 31) << 4);
        cp16(sw, g_wH + ((size_t)(by * 64 + row)) * 256 + ck * 8);
    }
    asm volatile("cp.async.commit_group;" ::: "memory");

    // ---- warp tiling: 16 warps = 4(M: 32 rows) x 4(N: 16 cols)
    const int wm = wid >> 2;
    const int wn = wid & 3;
    const int rl = lid & 15;
    const int kadd = lid >> 4;

    const int aR0 = wm * 32 + rl, aR1 = aR0 + 16;
    const uint32_t aO0 = aR0 * 512, aO1 = aR1 * 512;
    const int ax0 = aR0 & 7, ax1 = aR1 & 7;
    const int bR = wn * 16 + rl;
    const uint32_t bO = bR * 512;
    const int bxr = bR & 7;

    uint32_t fa0[2][4], fa1[2][4], fb[2][4];

    auto frag_ld = [&](int t, int pb) {
        const int ch = t * 2 + kadd;
        ldmx4(fa0[pb], sbase + OFF_A + aO0 + (((ch ^ ax0) & 31) << 4));
        ldmx4(fa1[pb], sbase + OFF_A + aO1 + (((ch ^ ax1) & 31) << 4));
        ldmx4(fb[pb],  sbase + OFF_B + bO  + (((ch ^ bxr) & 31) << 4));
    };

    float acc[2][2][4];
    #pragma unroll
    for (int i = 0; i < 2; ++i)
        #pragma unroll
        for (int j = 0; j < 2; ++j)
            #pragma unroll
            for (int q = 0; q < 4; ++q)
                acc[i][j][q] = 0.f;

    auto do_mma = [&](int pb) {
        mma16816(acc[0][0], fa0[pb], fb[pb][0], fb[pb][2]);
        mma16816(acc[0][1], fa0[pb], fb[pb][1], fb[pb][3]);
        mma16816(acc[1][0], fa1[pb], fb[pb][0], fb[pb][2]);
        mma16816(acc[1][1], fa1[pb], fb[pb][1], fb[pb][3]);
    };

    asm volatile("cp.async.wait_group 0;" ::: "memory");
    __syncthreads();

    // ---- straight 16-iter mainloop, fragment double-buffered
    frag_ld(0, 0);
    #pragma unroll
    for (int i = 0; i < 16; ++i) {
        if (i < 15) frag_ld(i + 1, (i + 1) & 1);
        do_mma(i & 1);
    }

    // ---- epilogue: band scale, bias, tanh, store
    const int qr = lid >> 2;
    const int qc = (lid & 3) * 2;
    #pragma unroll
    for (int mt = 0; mt < 2; ++mt) {
        #pragma unroll
        for (int h = 0; h < 2; ++h) {
            const int m = wm * 32 + mt * 16 + h * 8 + qr;   // 0..127
            const int n = m & 3, ls = m >> 2;
            const float scale = (n == 0) ? 1.0f
                              : (n == 1) ? ((ls < 16) ? 0.1f : 1.0f)
                              : 0.1f;
            float* orow = out + ((size_t)(bx * 128 + m)) * 256
                              + by * 64 + wn * 16 + qc;
            const float* brow = bias + by * 64 + wn * 16 + qc;
            #pragma unroll
            for (int nt = 0; nt < 2; ++nt) {
                float2 bb = *(const float2*)(brow + nt * 8);
                float2 o;
                o.x = tanh_fast(fmaf(scale, acc[mt][nt][h * 2 + 0], bb.x));
                o.y = tanh_fast(fmaf(scale, acc[mt][nt][h * 2 + 1], bb.y));
                *(float2*)(orow + nt * 8) = o;
            }
        }
    }
}

extern "C" void kernel_launch(void* const* d_in, const int* in_sizes, int n_in,
                              void* d_out, int out_size) {
    const float* enc  = (const float*)d_in[0];
    const float* W    = (const float*)d_in[1];
    const float* bias = (const float*)d_in[2];
    float* out = (float*)d_out;

    cvt_kernel<<<544, 256>>>(enc, W);    // 544*256 = 139264 = 131072 + 8192

    cudaFuncSetAttribute(spectral_hmma_kernel,
                         cudaFuncAttributeMaxDynamicSharedMemorySize, DYN_SMEM);
    dim3 grid(32, 4);
    spectral_hmma_kernel<<<grid, THREADS, DYN_SMEM>>>(bias, out);
}